// round 17
// baseline (speedup 1.0000x reference)
#include <cuda_runtime.h>
#include <cuda_bf16.h>
#include <cuda_fp16.h>
#include <stdint.h>
#include <math.h>

// Problem constants
#define T_   32
#define B_   256
#define DIN_ 4196
#define H_   1024
#define C_   151

#define KP_IN    4224                // DIN padded to mult of 64 (single-term fp16)
#define K_ST     H_                  // 1024 : single-term fp16 recurrence
#define K_OUT    (2 * H_)            // 2048 : output proj, HS 2-term [hi|lo] x W [hi|hi]
#define N_OUT    256                 // C padded to 256

#define NCHUNK   5                   // uneven PI chunks (timesteps): 12,8,6,4,2
static const int CH_END[NCHUNK] = {12, 20, 26, 30, 32};

// ---------------------------------------------------------------------------
// Scratch (static __device__ — no allocations allowed)
// ---------------------------------------------------------------------------
__device__ __half g_A2h[(size_t)T_ * B_ * KP_IN];    // x fp16  [8192, 4224]
__device__ __half g_B2h[(size_t)6 * H_ * KP_IN];     // W_in    [6144, 4224]
__device__ __half g_Bst[(size_t)5 * H_ * K_ST];      // W_state fp16 [5120, 1024]
__device__ __half g_Ah [(size_t)B_ * K_ST];          // h fp16  [256, 1024]
__device__ __half g_HS2[(size_t)T_ * B_ * K_OUT];    // HS 2-term [8192, 2048]
__device__ __half g_Wo2[(size_t)N_OUT * K_OUT];      // W_out [256, 2048] = [hi|hi]
__device__ __half g_PIh[(size_t)T_ * B_ * 6 * H_];   // PI as fp16
__device__ float g_PS [(size_t)B_ * 5 * H_];
__device__ float g_OUT[(size_t)T_ * B_ * N_OUT];     // padded logits
__device__ float g_CB [2 * (size_t)B_ * H_];
__device__ float g_bo [N_OUT];                       // padded output bias

// ---------------------------------------------------------------------------
// PTX helpers (baseline compute_103-safe: cp.async / ldmatrix / mma.sync only)
// ---------------------------------------------------------------------------
__device__ __forceinline__ uint32_t smem_u32(const void* p) {
    uint32_t a;
    asm("{ .reg .u64 t; cvta.to.shared.u64 t, %1; cvt.u32.u64 %0, t; }"
        : "=r"(a) : "l"(p));
    return a;
}
__device__ __forceinline__ void cp16(uint32_t d, const void* s) {
    asm volatile("cp.async.cg.shared.global [%0], [%1], 16;" :: "r"(d), "l"(s));
}
__device__ __forceinline__ void cp_commit() {
    asm volatile("cp.async.commit_group;" ::: "memory");
}
template <int N> __device__ __forceinline__ void cp_wait() {
    asm volatile("cp.async.wait_group %0;" :: "n"(N) : "memory");
}
__device__ __forceinline__ void ldsm4(uint32_t* r, uint32_t addr) {
    asm volatile("ldmatrix.sync.aligned.m8n8.x4.shared.b16 {%0,%1,%2,%3}, [%4];"
                 : "=r"(r[0]), "=r"(r[1]), "=r"(r[2]), "=r"(r[3]) : "r"(addr));
}
__device__ __forceinline__ void mma_fp16(float* c, const uint32_t* a, const uint32_t* b) {
    asm volatile(
        "mma.sync.aligned.m16n8k16.row.col.f32.f16.f16.f32 "
        "{%0,%1,%2,%3}, {%4,%5,%6,%7}, {%8,%9}, {%0,%1,%2,%3};"
        : "+f"(c[0]), "+f"(c[1]), "+f"(c[2]), "+f"(c[3])
        : "r"(a[0]), "r"(a[1]), "r"(a[2]), "r"(a[3]), "r"(b[0]), "r"(b[1]));
}

// SW128 swizzle for 128B rows (8-row x 128B atoms): conflict-free ldmatrix
#define SW128(o) ((o) ^ (((o) >> 3) & 0x70))

// ---------------------------------------------------------------------------
// fp16 tensor-core GEMM, BK=64 (128B rows, SW128):
// C[M,N] = A[M,K]·B[N,K]^T + bias[N].  K % 64 == 0.
// OUT_HALF=1 stores C as __half (half2 packed), else fp32.
// ---------------------------------------------------------------------------
template<int BM, int BN, int WM, int WN, int STAGES, int MAXCTA, int OUT_HALF,
         int THREADS>
__global__ void __launch_bounds__(THREADS, MAXCTA)
mma_gemm(const void* __restrict__ Av, const void* __restrict__ Bv,
         const float* __restrict__ bias, void* __restrict__ Cv,
         int M, int N, int K) {
    constexpr int STG = (BM + BN) * 128;     // bytes per stage (BK=64 fp16 = 128B/row)
    constexpr int MW = BM / WM;
    constexpr int NW = BN / WN;
    static_assert(MW * NW == THREADS / 32, "warp count mismatch");
    constexpr int MT = WM / 16;
    constexpr int NT = WN / 8;
    constexpr int NP = WN / 16;

    extern __shared__ char smem[];
    const uint32_t sb = smem_u32(smem);
    const char* A = (const char*)Av;
    const char* B = (const char*)Bv;
    const int tid = threadIdx.x;
    const int wid = tid >> 5;
    const int lane = tid & 31;
    const int wm = wid % MW;
    const int wn = wid / MW;
    const int l8 = lane & 7;
    const int sel = lane >> 3;
    const int m0 = blockIdx.y * BM;
    const int n0 = blockIdx.x * BN;
    const int KT = K / 64;

    auto load_stage = [&](int s, int kt) {
        const char* Ag = A + ((size_t)m0 * K + kt * 64) * 2;
        const char* Bg = B + ((size_t)n0 * K + kt * 64) * 2;
        const uint32_t stb = sb + s * STG;
#pragma unroll
        for (int i = tid; i < (BM + BN) * 8; i += THREADS) {
            if (i < BM * 8) {
                int row = i >> 3, c = i & 7;
                cp16(stb + SW128(row * 128 + c * 16), Ag + (size_t)row * K * 2 + c * 16);
            } else {
                int j = i - BM * 8;
                int row = j >> 3, c = j & 7;
                cp16(stb + BM * 128 + SW128(row * 128 + c * 16),
                     Bg + (size_t)row * K * 2 + c * 16);
            }
        }
    };

    float acc[MT][NT][4];
#pragma unroll
    for (int i = 0; i < MT; i++)
#pragma unroll
        for (int j = 0; j < NT; j++)
#pragma unroll
            for (int v = 0; v < 4; v++) acc[i][j][v] = 0.f;

#pragma unroll
    for (int s = 0; s < STAGES - 1; s++) {
        if (s < KT) load_stage(s, s);
        cp_commit();
    }

    for (int kt = 0; kt < KT; ++kt) {
        cp_wait<STAGES - 2>();
        __syncthreads();
        const int nk = kt + STAGES - 1;
        if (nk < KT) load_stage(nk % STAGES, nk);
        cp_commit();

        const uint32_t stb = sb + (kt % STAGES) * STG;
        const uint32_t stbB = stb + BM * 128;
#pragma unroll
        for (int ks = 0; ks < 4; ks++) {
            uint32_t ar[MT][4];
            uint32_t br[NP][4];
#pragma unroll
            for (int mt = 0; mt < MT; mt++) {
                int row = wm * WM + mt * 16 + l8 + (sel & 1) * 8;
                int ch = ks * 2 + (sel >> 1);
                ldsm4(ar[mt], stb + SW128(row * 128 + ch * 16));
            }
#pragma unroll
            for (int p = 0; p < NP; p++) {
                int row = wn * WN + p * 16 + l8 + (sel >> 1) * 8;
                int ch = ks * 2 + (sel & 1);
                ldsm4(br[p], stbB + SW128(row * 128 + ch * 16));
            }
#pragma unroll
            for (int mt = 0; mt < MT; mt++)
#pragma unroll
                for (int nt = 0; nt < NT; nt++)
                    mma_fp16(acc[mt][nt], ar[mt], &br[nt >> 1][(nt & 1) * 2]);
        }
    }

    const int g4 = lane >> 2;
    const int t4 = lane & 3;
#pragma unroll
    for (int mt = 0; mt < MT; mt++) {
#pragma unroll
        for (int nt = 0; nt < NT; nt++) {
            const int r = m0 + wm * WM + mt * 16 + g4;
            const int col = n0 + wn * WN + nt * 8 + 2 * t4;
            const float b0 = bias[col], b1 = bias[col + 1];
            if (OUT_HALF) {
                __half* C = (__half*)Cv;
                __half2 v0 = __floats2half2_rn(acc[mt][nt][0] + b0, acc[mt][nt][1] + b1);
                __half2 v1 = __floats2half2_rn(acc[mt][nt][2] + b0, acc[mt][nt][3] + b1);
                *reinterpret_cast<__half2*>(&C[(size_t)r * N + col]) = v0;
                *reinterpret_cast<__half2*>(&C[(size_t)(r + 8) * N + col]) = v1;
            } else {
                float* C = (float*)Cv;
                float2 v0 = make_float2(acc[mt][nt][0] + b0, acc[mt][nt][1] + b1);
                float2 v1 = make_float2(acc[mt][nt][2] + b0, acc[mt][nt][3] + b1);
                *reinterpret_cast<float2*>(&C[(size_t)r * N + col]) = v0;
                *reinterpret_cast<float2*>(&C[(size_t)(r + 8) * N + col]) = v1;
            }
        }
    }
}

// ---------------------------------------------------------------------------
// Conversions
// ---------------------------------------------------------------------------
__global__ void cast_f16_v8(const float* __restrict__ src, __half* __restrict__ dst,
                            int K, int Kp, int total8) {
    int idx = blockIdx.x * 256 + threadIdx.x;
    if (idx >= total8) return;
    const int kq = Kp >> 3;
    int r = idx / kq, k = (idx - r * kq) << 3;
    const float* srow = src + (size_t)r * K;
    float4 v0 = make_float4(0.f, 0.f, 0.f, 0.f);
    float4 v1 = make_float4(0.f, 0.f, 0.f, 0.f);
    if (k < K)     v0 = *reinterpret_cast<const float4*>(&srow[k]);
    if (k + 4 < K) v1 = *reinterpret_cast<const float4*>(&srow[k + 4]);
    __half2* row = reinterpret_cast<__half2*>(dst + (size_t)r * Kp + k);
    row[0] = __floats2half2_rn(v0.x, v0.y);
    row[1] = __floats2half2_rn(v0.z, v0.w);
    row[2] = __floats2half2_rn(v1.x, v1.y);
    row[3] = __floats2half2_rn(v1.z, v1.w);
}
__global__ void cast_f16_v4(const float* __restrict__ src, __half* __restrict__ dst,
                            int K, int Kp, int total4) {
    int idx = blockIdx.x * 256 + threadIdx.x;
    if (idx >= total4) return;
    const int kq = Kp >> 2;
    int r = idx / kq, k = (idx - r * kq) << 2;
    float4 v = make_float4(0.f, 0.f, 0.f, 0.f);
    if (k < K) v = *reinterpret_cast<const float4*>(&src[(size_t)r * K + k]);
    __half2* row = reinterpret_cast<__half2*>(dst + (size_t)r * Kp + k);
    row[0] = __floats2half2_rn(v.x, v.y);
    row[1] = __floats2half2_rn(v.z, v.w);
}
__global__ void split_Wo_v4(const float* __restrict__ src, __half* __restrict__ dst,
                            int total4) {
    int idx = blockIdx.x * 256 + threadIdx.x;
    if (idx >= total4) return;
    const int kq = H_ >> 2;
    int r = idx / kq, k = (idx - r * kq) << 2;
    float4 v = make_float4(0.f, 0.f, 0.f, 0.f);
    if (r < C_) v = *reinterpret_cast<const float4*>(&src[(size_t)r * H_ + k]);
    __half2 h0 = __floats2half2_rn(v.x, v.y);
    __half2 h1 = __floats2half2_rn(v.z, v.w);
    __half2* row0 = reinterpret_cast<__half2*>(dst + (size_t)r * K_OUT + k);
    __half2* row1 = reinterpret_cast<__half2*>(dst + (size_t)r * K_OUT + H_ + k);
    row0[0] = h0; row0[1] = h1;
    row1[0] = h0; row1[1] = h1;
}
__global__ void cast_h0_v4(const float* __restrict__ src, __half* __restrict__ dst,
                           int total4) {
    int idx = blockIdx.x * 256 + threadIdx.x;
    if (idx >= total4) return;
    float4 v = *reinterpret_cast<const float4*>(&src[idx << 2]);
    __half2* d = reinterpret_cast<__half2*>(dst + (idx << 2));
    d[0] = __floats2half2_rn(v.x, v.y);
    d[1] = __floats2half2_rn(v.z, v.w);
}
__global__ void pad_bias(const float* __restrict__ src, float* __restrict__ dst) {
    int i = threadIdx.x;
    if (i < N_OUT) dst[i] = (i < C_) ? src[i] : 0.f;
}
__global__ void unpad_out(const float* __restrict__ src, float* __restrict__ dst,
                          int total) {
    int idx = blockIdx.x * 256 + threadIdx.x;
    if (idx >= total) return;
    int r = idx / C_, c = idx - r * C_;
    dst[idx] = src[(size_t)r * N_OUT + c];
}

// ---------------------------------------------------------------------------
// Fused gates + dropout (pi fp16); emits c_out, fp16 h, 2-term HS row
// ---------------------------------------------------------------------------
__device__ __forceinline__ float sigf(float x) { return 1.f / (1.f + expf(-x)); }

__global__ void gates_kernel(const __half* __restrict__ pi, const float* __restrict__ ps,
                             const float* __restrict__ c_in, float* __restrict__ c_out,
                             const float* __restrict__ mask,
                             __half* __restrict__ Ah, __half* __restrict__ hs2t) {
    const int idx = blockIdx.x * blockDim.x + threadIdx.x;
    if (idx >= B_ * H_) return;
    const int b = idx / H_;
    const int j = idx - b * H_;
    const __half* pib = pi + (size_t)b * 6 * H_;
    const float* psb = ps + (size_t)b * 5 * H_;

    const float i_g = sigf(__half2float(pib[0 * H_ + j]) + psb[0 * H_ + j]);
    const float f_g = sigf(__half2float(pib[1 * H_ + j]) + psb[1 * H_ + j]);
    const float m_i = tanhf(__half2float(pib[2 * H_ + j]) + psb[2 * H_ + j]);
    const float o_g = sigf(__half2float(pib[3 * H_ + j]) + psb[3 * H_ + j]);
    const float mem = i_g * m_i + f_g * c_in[idx];
    float out = o_g * tanhf(mem);
    const float hw = sigf(__half2float(pib[4 * H_ + j]) + psb[4 * H_ + j]);
    out = hw * out + (1.f - hw) * __half2float(pib[5 * H_ + j]);
    out *= mask[idx];
    c_out[idx] = mem;

    __half hi = __float2half(out);
    __half lo = __float2half(out - __half2float(hi));
    Ah[idx] = hi;
    __half* row = hs2t + (size_t)b * K_OUT;
    row[j] = hi; row[H_ + j] = lo;
}

// ---------------------------------------------------------------------------
extern "C" void kernel_launch(void* const* d_in, const int* in_sizes, int n_in,
                              void* d_out, int out_size) {
    const float* x       = (const float*)d_in[0];
    const float* h0      = (const float*)d_in[1];
    const float* c0      = (const float*)d_in[2];
    const float* mask    = (const float*)d_in[3];
    const float* W_in    = (const float*)d_in[4];
    const float* b_in    = (const float*)d_in[5];
    const float* W_state = (const float*)d_in[6];
    const float* b_state = (const float*)d_in[7];
    const float* W_out   = (const float*)d_in[8];
    const float* b_out   = (const float*)d_in[9];
    float* out = (float*)d_out;

    __half *A2h, *B2h, *Bst, *Ah, *HS2, *Wo2, *PIh;
    float *PS, *OUT, *CB, *BO;
    cudaGetSymbolAddress((void**)&A2h, g_A2h);
    cudaGetSymbolAddress((void**)&B2h, g_B2h);
    cudaGetSymbolAddress((void**)&Bst, g_Bst);
    cudaGetSymbolAddress((void**)&Ah, g_Ah);
    cudaGetSymbolAddress((void**)&HS2, g_HS2);
    cudaGetSymbolAddress((void**)&Wo2, g_Wo2);
    cudaGetSymbolAddress((void**)&PIh, g_PIh);
    cudaGetSymbolAddress((void**)&PS, g_PS);
    cudaGetSymbolAddress((void**)&OUT, g_OUT);
    cudaGetSymbolAddress((void**)&CB, g_CB);
    cudaGetSymbolAddress((void**)&BO, g_bo);

    static cudaStream_t s2 = nullptr;
    static cudaEvent_t evFork = nullptr;
    static cudaEvent_t evPI[NCHUNK];
    static cudaEvent_t evX[NCHUNK];
    static cudaEvent_t evG23 = nullptr;
    static cudaEvent_t evOutA = nullptr;
    if (!s2) {
        cudaStreamCreateWithFlags(&s2, cudaStreamNonBlocking);
        cudaEventCreateWithFlags(&evFork, cudaEventDisableTiming);
        cudaEventCreateWithFlags(&evG23, cudaEventDisableTiming);
        cudaEventCreateWithFlags(&evOutA, cudaEventDisableTiming);
        for (int i = 0; i < NCHUNK; i++) {
            cudaEventCreateWithFlags(&evPI[i], cudaEventDisableTiming);
            cudaEventCreateWithFlags(&evX[i], cudaEventDisableTiming);
        }
    }

    constexpr int SMEM_BIG = (128 + 128) * 128 * 3;  // 98304 (3 stages, BK=64)
    constexpr int SMEM_REC = (64 + 128) * 128 * 3;   // 73728 (3 stages, BK=64)
    cudaFuncSetAttribute((const void*)mma_gemm<128, 128, 64, 64, 3, 2, 1, 128>,
                         cudaFuncAttributeMaxDynamicSharedMemorySize, SMEM_BIG);
    cudaFuncSetAttribute((const void*)mma_gemm<64, 128, 32, 32, 3, 2, 0, 256>,
                         cudaFuncAttributeMaxDynamicSharedMemorySize, SMEM_REC);

    const size_t BH = (size_t)B_ * H_;
    const int T_SPLIT = 24;                     // output proj split point

    // ---- fork side stream off the capture stream ----
    cudaEventRecord(evFork, 0);
    cudaStreamWaitEvent(s2, evFork, 0);

    // ---- capture stream: per-chunk x casts (overlap s2's W_in cast) ----
    {
        int start = 0;
        for (int c = 0; c < NCHUNK; c++) {
            int rows = (CH_END[c] - start) * B_;
            int tot8 = rows * KP_IN / 8;
            cast_f16_v8<<<(tot8 + 255) / 256, 256>>>(
                x + (size_t)start * B_ * DIN_, A2h + (size_t)start * B_ * KP_IN,
                DIN_, KP_IN, tot8);
            cudaEventRecord(evX[c], 0);
            start = CH_END[c];
        }
    }

    // ---- stream s2: W_in cast, then PI GEMM chunks (uneven) ----
    {
        int tot8 = 6 * H_ * KP_IN / 8;
        cast_f16_v8<<<(tot8 + 255) / 256, 256, 0, s2>>>(W_in, B2h, DIN_, KP_IN, tot8);
    }
    {
        int start = 0;
        for (int c = 0; c < NCHUNK; c++) {
            int rows = (CH_END[c] - start) * B_;
            cudaStreamWaitEvent(s2, evX[c], 0);
            dim3 grid((6 * H_) / 128, rows / 128);
            mma_gemm<128, 128, 64, 64, 3, 2, 1, 128><<<grid, 128, SMEM_BIG, s2>>>(
                A2h + (size_t)start * B_ * KP_IN, B2h, b_in,
                PIh + (size_t)start * B_ * 6 * H_, rows, 6 * H_, KP_IN);
            cudaEventRecord(evPI[c], s2);
            start = CH_END[c];
        }
    }

    // ---- capture stream: conversions for recurrence + output proj ----
    {
        int tot4 = 5 * H_ * H_ / 4;
        cast_f16_v4<<<(tot4 + 255) / 256, 256>>>(W_state, Bst, H_, H_, tot4);
    }
    {
        int tot4 = B_ * H_ / 4;
        cast_h0_v4<<<(tot4 + 255) / 256, 256>>>(h0, Ah, tot4);
    }
    {
        int tot4 = N_OUT * H_ / 4;
        split_Wo_v4<<<(tot4 + 255) / 256, 256>>>(W_out, Wo2, tot4);
        pad_bias<<<1, N_OUT>>>(b_out, BO);
    }

    // ---- recurrence chain (single-term fp16, K=1024) ----
    {
        int chunk = 0, start = 0;
        for (int t = 0; t < T_; ++t) {
            const float* csrc = (t == 0) ? c0 : CB + (size_t)((t - 1) & 1) * BH;
            float* cdst = CB + (size_t)(t & 1) * BH;
            const __half* pit = PIh + (size_t)t * B_ * 6 * H_;
            __half* hs2t = HS2 + (size_t)t * B_ * K_OUT;

            dim3 grid((5 * H_) / 128, B_ / 64);
            mma_gemm<64, 128, 32, 32, 3, 2, 0, 256><<<grid, 256, SMEM_REC>>>(
                Ah, Bst, b_state, PS, B_, 5 * H_, K_ST);

            if (t == start) {
                cudaStreamWaitEvent(0, evPI[chunk], 0);
            }
            gates_kernel<<<(B_ * H_) / 256, 256>>>(pit, PS, csrc, cdst, mask, Ah, hs2t);

            if (t == T_SPLIT - 1) cudaEventRecord(evG23, 0);
            if (t + 1 == CH_END[chunk] && chunk + 1 < NCHUNK) {
                chunk++; start = CH_END[chunk - 1];
            }
        }
    }

    // ---- output projection piece A (t < 24) on s2, overlapping chain tail ----
    {
        cudaStreamWaitEvent(s2, evG23, 0);
        dim3 grid(N_OUT / 128, (T_SPLIT * B_) / 64);
        mma_gemm<64, 128, 32, 32, 3, 2, 0, 256><<<grid, 256, SMEM_REC, s2>>>(
            HS2, Wo2, BO, OUT, T_SPLIT * B_, N_OUT, K_OUT);
        cudaEventRecord(evOutA, s2);
    }
    // ---- output projection piece B (t >= 24) on capture stream ----
    {
        dim3 grid(N_OUT / 128, ((T_ - T_SPLIT) * B_) / 64);
        mma_gemm<64, 128, 32, 32, 3, 2, 0, 256><<<grid, 256, SMEM_REC>>>(
            HS2 + (size_t)T_SPLIT * B_ * K_OUT, Wo2, BO,
            OUT + (size_t)T_SPLIT * B_ * N_OUT, (T_ - T_SPLIT) * B_, N_OUT, K_OUT);
    }
    // ---- join + unpad ----
    cudaStreamWaitEvent(0, evOutA, 0);
    {
        int tot = T_ * B_ * C_;
        unpad_out<<<(tot + 255) / 256, 256>>>(OUT, out, tot);
    }
}